// round 5
// baseline (speedup 1.0000x reference)
#include <cuda_runtime.h>
#include <cstdint>

typedef unsigned long long u64;

#define E_CNT 100000
#define NDST  10000
#define OUTC  2048
#define MTILE 128
#define NBLK  ((E_CNT + MTILE - 1) / MTILE)

// ---------------- small device scratch (CSR only) ----------------
__device__ int g_counts[NDST];
__device__ int g_cursor[NDST];
__device__ int g_eid   [E_CNT];

// ---------------- prologue kernels ----------------
__global__ void zero_cnt_k() {
    int i = blockIdx.x * blockDim.x + threadIdx.x;
    if (i < NDST) g_counts[i] = 0;
}
__global__ void hist_k(const int* __restrict__ dst) {
    int e = blockIdx.x * blockDim.x + threadIdx.x;
    if (e < E_CNT) atomicAdd(&g_counts[dst[e]], 1);
}
__global__ void scan_k() {
    __shared__ int ss[1024];
    const int tid = threadIdx.x;
    const int CH = 10;
    int base = tid * CH, loc[CH], s = 0;
#pragma unroll
    for (int i = 0; i < CH; i++) {
        int idx = base + i;
        int v = (idx < NDST) ? g_counts[idx] : 0;
        loc[i] = s; s += v;
    }
    ss[tid] = s; __syncthreads();
    for (int off = 1; off < 1024; off <<= 1) {
        int v = 0;
        if (tid >= off) v = ss[tid - off];
        __syncthreads();
        if (tid >= off) ss[tid] += v;
        __syncthreads();
    }
    int excl = (tid == 0) ? 0 : ss[tid - 1];
#pragma unroll
    for (int i = 0; i < CH; i++) {
        int idx = base + i;
        if (idx < NDST) g_cursor[idx] = excl + loc[i];
    }
}
__global__ void fill_k(const int* __restrict__ dst) {
    int e = blockIdx.x * blockDim.x + threadIdx.x;
    if (e < E_CNT) {
        int p = atomicAdd(&g_cursor[dst[e]], 1);
        g_eid[p] = e;
    }
}
__global__ void zero_out_k(float4* __restrict__ out, int n4) {
    int i = blockIdx.x * blockDim.x + threadIdx.x;
    if (i < n4) out[i] = make_float4(0.f, 0.f, 0.f, 0.f);
}

// ---------------- packed fp32x2 helpers ----------------
__device__ __forceinline__ void ffma2(u64& d, u64 a, u64 b) {
    asm("fma.rn.f32x2 %0, %1, %2, %0;" : "+l"(d) : "l"(a), "l"(b));
}
__device__ __forceinline__ u64 pack2(float x) {
    u64 r; asm("mov.b64 %0, {%1, %1};" : "=l"(r) : "f"(x)); return r;
}
__device__ __forceinline__ float2 unpack2(u64 v) {
    float2 f; asm("mov.b64 {%0, %1}, %2;" : "=f"(f.x), "=f"(f.y) : "l"(v)); return f;
}
__device__ __forceinline__ float silu_f(float x) {
    return x / (1.f + __expf(-x));
}

// ---------------- smem layout (float offsets) ----------------
#define F_HS   0            // Hs  [128][128]  64KB
#define F_EMB  16384        // EMB [128][64] / Ws [64][128]  32KB union
#define F_TPW  24576        // TPW [128][128] 64KB (W1s [64][128] aliases 1st half)
#define F_SHS  40960        // SHs [128][16]  8KB
#define F_END  43008
#define SMEM_BYTES (F_END * 4 + 384 * 4)

// ---------------- fused kernel: MLP (f32x2) + TP + segment scatter ----------
__global__ __launch_bounds__(256) void fused_k(
    const float* __restrict__ src_features,
    const float* __restrict__ edge_sh,
    const float* __restrict__ edge_emb,
    const float* __restrict__ W1,
    const float* __restrict__ W2,
    const int*   __restrict__ src,
    const int*   __restrict__ dst,
    float*       __restrict__ out)
{
    extern __shared__ float sm[];
    float* Hs  = sm + F_HS;
    float* EMB = sm + F_EMB;  float* Ws  = EMB;
    float* TPW = sm + F_TPW;  float* W1s = TPW;
    float* SHs = sm + F_SHS;
    int*   Es  = (int*)(sm + F_END);
    int*   Ss  = Es + 128;
    int*   Ds  = Ss + 128;

    const int tid  = threadIdx.x;
    const int wid  = tid >> 5;
    const int lane = tid & 31;
    const int r0   = wid * 16;     // 16 rows per warp (warp-uniform!)
    const int c0   = lane * 4;     // 4 cols per lane

    // ---- stage edge metadata (pads replicate last edge; SH pads -> 0) ----
    const int pos0 = blockIdx.x * MTILE;
    const int nE   = (E_CNT - pos0 < MTILE) ? (E_CNT - pos0) : MTILE;
    if (tid < 128) {
        int sl = (tid < nE) ? tid : (nE - 1);
        int e  = g_eid[pos0 + sl];
        Es[tid] = e; Ss[tid] = src[e]; Ds[tid] = dst[e];
    }
    __syncthreads();

    // ---- stage EMB (gathered), W1s (scaled), SHs ----
#pragma unroll
    for (int t = 0; t < 8; t++) {              // EMB: 128 x 16 float4
        int li = tid + t * 256;
        int slot = li >> 4, f = li & 15;
        float4 v = *(const float4*)&edge_emb[(size_t)Es[slot] * 64 + f * 4];
        *(float4*)&EMB[slot * 64 + f * 4] = v;
    }
#pragma unroll
    for (int t = 0; t < 8; t++) {              // W1s: 64 x 32 float4, *1/8
        int li = tid + t * 256;
        int r = li >> 5, f = li & 31;
        float4 v = *(const float4*)&W1[(size_t)r * 128 + f * 4];
        v.x *= 0.125f; v.y *= 0.125f; v.z *= 0.125f; v.w *= 0.125f;
        *(float4*)&W1s[r * 128 + f * 4] = v;
    }
#pragma unroll
    for (int t = 0; t < 2; t++) {              // SHs: 128 x 4 float4 (zero pads)
        int li = tid + t * 256;
        int slot = li >> 2, j = li & 3;
        float4 v = make_float4(0.f, 0.f, 0.f, 0.f);
        if (slot < nE)
            v = *(const float4*)&edge_sh[(size_t)Es[slot] * 16 + j * 4];
        *(float4*)&SHs[slot * 16 + j * 4] = v;
    }
    __syncthreads();

    // ---- GEMM1: Hs = silu(EMB @ W1s), M128 N128 K64, fp32x2 ----
    {
        u64 acc[16][2];
#pragma unroll
        for (int i = 0; i < 16; i++) { acc[i][0] = 0ull; acc[i][1] = 0ull; }

#pragma unroll 2
        for (int k = 0; k < 64; k += 4) {
            u64 rb[4][2];
#pragma unroll
            for (int kk = 0; kk < 4; kk++) {
                rb[kk][0] = *(const u64*)&W1s[(k + kk) * 128 + c0];
                rb[kk][1] = *(const u64*)&W1s[(k + kk) * 128 + c0 + 2];
            }
#pragma unroll
            for (int i = 0; i < 16; i++) {
                float4 ra = *(const float4*)&EMB[(r0 + i) * 64 + k];  // broadcast
                u64 a0 = pack2(ra.x), a1 = pack2(ra.y);
                u64 a2 = pack2(ra.z), a3 = pack2(ra.w);
                ffma2(acc[i][0], a0, rb[0][0]); ffma2(acc[i][1], a0, rb[0][1]);
                ffma2(acc[i][0], a1, rb[1][0]); ffma2(acc[i][1], a1, rb[1][1]);
                ffma2(acc[i][0], a2, rb[2][0]); ffma2(acc[i][1], a2, rb[2][1]);
                ffma2(acc[i][0], a3, rb[3][0]); ffma2(acc[i][1], a3, rb[3][1]);
            }
        }
#pragma unroll
        for (int i = 0; i < 16; i++) {
            float2 p0 = unpack2(acc[i][0]), p1 = unpack2(acc[i][1]);
            float4 v;
            v.x = silu_f(p0.x); v.y = silu_f(p0.y);
            v.z = silu_f(p1.x); v.w = silu_f(p1.y);
            *(float4*)&Hs[(r0 + i) * 128 + c0] = v;
        }
    }
    __syncthreads();   // Hs ready; EMB (-> Ws) and W1s (-> TPW) now dead

    // ---- per-l: GEMM2 (fp32x2) + fold x + run-length segment scatter ----
    const float w2s = 0.08838834764831845f;  // 1/sqrt(128)

    for (int l = 0; l < 4; l++) {
        u64 acc2[16][2];
#pragma unroll
        for (int i = 0; i < 16; i++) { acc2[i][0] = 0ull; acc2[i][1] = 0ull; }

        for (int k0 = 0; k0 < 128; k0 += 64) {
            // stage Ws[64][128] = W2[k0..k0+63][l*128..+128] * w2s
#pragma unroll
            for (int t = 0; t < 8; t++) {
                int li = tid + t * 256;
                int r = li >> 5, f = li & 31;
                float4 v = *(const float4*)&W2[(size_t)(k0 + r) * 512 + l * 128 + f * 4];
                v.x *= w2s; v.y *= w2s; v.z *= w2s; v.w *= w2s;
                *(float4*)&Ws[r * 128 + f * 4] = v;
            }
            __syncthreads();

#pragma unroll 2
            for (int k = 0; k < 64; k += 4) {
                u64 rb[4][2];
#pragma unroll
                for (int kk = 0; kk < 4; kk++) {
                    rb[kk][0] = *(const u64*)&Ws[(k + kk) * 128 + c0];
                    rb[kk][1] = *(const u64*)&Ws[(k + kk) * 128 + c0 + 2];
                }
#pragma unroll
                for (int i = 0; i < 16; i++) {
                    float4 ra = *(const float4*)&Hs[(r0 + i) * 128 + k0 + k];
                    u64 a0 = pack2(ra.x), a1 = pack2(ra.y);
                    u64 a2 = pack2(ra.z), a3 = pack2(ra.w);
                    ffma2(acc2[i][0], a0, rb[0][0]); ffma2(acc2[i][1], a0, rb[0][1]);
                    ffma2(acc2[i][0], a1, rb[1][0]); ffma2(acc2[i][1], a1, rb[1][1]);
                    ffma2(acc2[i][0], a2, rb[2][0]); ffma2(acc2[i][1], a2, rb[2][1]);
                    ffma2(acc2[i][0], a3, rb[3][0]); ffma2(acc2[i][1], a3, rb[3][1]);
                }
            }
            __syncthreads();   // Ws dead before restage / next phase
        }

        // fold: TPW[row][c] = acc2 * x_src[src[row]][c]   (x via L2, coalesced)
#pragma unroll
        for (int i = 0; i < 16; i++) {
            float4 xv = *(const float4*)&src_features[(size_t)Ss[r0 + i] * 128 + c0];
            float2 p0 = unpack2(acc2[i][0]), p1 = unpack2(acc2[i][1]);
            float4 v;
            v.x = p0.x * xv.x; v.y = p0.y * xv.y;
            v.z = p1.x * xv.z; v.w = p1.y * xv.w;
            *(float4*)&TPW[(r0 + i) * 128 + c0] = v;
        }
        __syncthreads();

        // scatter: run-length reduce over 128 dst-sorted edges
        {
            const int d    = 2 * l + 1;
            const int soff = l * l;
            const int ob   = (l == 0) ? 0 : (l == 1) ? 128 : (l == 2) ? 512 : 1152;
            const int ncol = 128 * d;
            for (int q = tid; q < ncol; q += 256) {
                const int c = q / d;
                const int s = q - c * d;
                float a = 0.f;
                int cur = Ds[0];
#pragma unroll 4
                for (int t = 0; t < 128; t++) {
                    int dn = Ds[t];
                    if (dn != cur) {
                        atomicAdd(&out[(size_t)cur * OUTC + ob + q], a);
                        a = 0.f; cur = dn;
                    }
                    a += TPW[t * 128 + c] * SHs[t * 16 + soff + s];
                }
                atomicAdd(&out[(size_t)cur * OUTC + ob + q], a);
            }
        }
        __syncthreads();
    }
}

// ---------------- launch ----------------
extern "C" void kernel_launch(void* const* d_in, const int* in_sizes, int n_in,
                              void* d_out, int out_size)
{
    const float* src_features = (const float*)d_in[0];
    const float* edge_sh      = (const float*)d_in[1];
    const float* edge_emb     = (const float*)d_in[2];
    const float* W1           = (const float*)d_in[3];
    const float* W2           = (const float*)d_in[4];
    const int*   src          = (const int*)d_in[5];
    const int*   dst          = (const int*)d_in[6];
    float*       out          = (float*)d_out;
    (void)in_sizes; (void)n_in; (void)out_size;

    static bool attr_done = false;
    if (!attr_done) {
        cudaFuncSetAttribute(fused_k, cudaFuncAttributeMaxDynamicSharedMemorySize,
                             SMEM_BYTES);
        attr_done = true;
    }

    // CSR build
    zero_cnt_k<<<(NDST + 255) / 256, 256>>>();
    hist_k<<<(E_CNT + 255) / 256, 256>>>(dst);
    scan_k<<<1, 1024>>>();
    fill_k<<<(E_CNT + 255) / 256, 256>>>(dst);

    // zero output (atomic accumulation target)
    const int n4 = NDST * OUTC / 4;
    zero_out_k<<<(n4 + 255) / 256, 256>>>((float4*)out, n4);

    // fused MLP + TP + scatter
    fused_k<<<NBLK, 256, SMEM_BYTES>>>(src_features, edge_sh, edge_emb,
                                       W1, W2, src, dst, out);
}

// round 6
// speedup vs baseline: 2.0904x; 2.0904x over previous
#include <cuda_runtime.h>
#include <cstdint>

#define E_CNT 100000
#define NDST  10000
#define OUTC  2048

// ---------------- small device scratch (CSR only) ----------------
__device__ int g_counts[NDST];
__device__ int g_cursor[NDST];
__device__ int g_eid   [E_CNT];

// ---------------- prologue kernels ----------------
__global__ void zero_cnt_k() {
    int i = blockIdx.x * blockDim.x + threadIdx.x;
    if (i < NDST) g_counts[i] = 0;
}
__global__ void hist_k(const int* __restrict__ dst) {
    int e = blockIdx.x * blockDim.x + threadIdx.x;
    if (e < E_CNT) atomicAdd(&g_counts[dst[e]], 1);
}
__global__ void scan_k() {
    __shared__ int ss[1024];
    const int tid = threadIdx.x;
    const int CH = 10;
    int base = tid * CH, loc[CH], s = 0;
#pragma unroll
    for (int i = 0; i < CH; i++) {
        int idx = base + i;
        int v = (idx < NDST) ? g_counts[idx] : 0;
        loc[i] = s; s += v;
    }
    ss[tid] = s; __syncthreads();
    for (int off = 1; off < 1024; off <<= 1) {
        int v = 0;
        if (tid >= off) v = ss[tid - off];
        __syncthreads();
        if (tid >= off) ss[tid] += v;
        __syncthreads();
    }
    int excl = (tid == 0) ? 0 : ss[tid - 1];
#pragma unroll
    for (int i = 0; i < CH; i++) {
        int idx = base + i;
        if (idx < NDST) g_cursor[idx] = excl + loc[i];
    }
}
__global__ void fill_k(const int* __restrict__ dst) {
    int e = blockIdx.x * blockDim.x + threadIdx.x;
    if (e < E_CNT) {
        int p = atomicAdd(&g_cursor[dst[e]], 1);
        g_eid[p] = e;
    }
}
__global__ void zero_out_k(float4* __restrict__ out, int n4) {
    int i = blockIdx.x * blockDim.x + threadIdx.x;
    if (i < n4) out[i] = make_float4(0.f, 0.f, 0.f, 0.f);
}

// ---------------- smem layout (float offsets) ----------------
// Hs  [64][128] 32KB | Ws [64][128] 32KB (EMB [64][64] aliases) |
// TPW [64][128] 32KB (W1s aliases) | SHs [64][16] 4KB | 192 ints
#define F_HS   0
#define F_WS   8192
#define F_TPW  16384
#define F_SHS  24576
#define F_END  25600
#define SMEM_BYTES (F_END * 4 + 192 * 4)

// ---------------- fused kernel: MLP + TP + segment scatter -----------------
__global__ __launch_bounds__(256, 2) void fused_k(
    const float* __restrict__ src_features,
    const float* __restrict__ edge_sh,
    const float* __restrict__ edge_emb,
    const float* __restrict__ W1,
    const float* __restrict__ W2,
    const int*   __restrict__ src,
    const int*   __restrict__ dst,
    float*       __restrict__ out)
{
    extern __shared__ float sm[];
    float* Hs  = sm + F_HS;
    float* Ws  = sm + F_WS;   float* EMB = Ws;    // union
    float* TPW = sm + F_TPW;  float* W1s = TPW;   // union
    float* SHs = sm + F_SHS;
    int*   Es  = (int*)(sm + F_END);
    int*   Ss  = Es + 64;
    int*   Ds  = Ss + 64;

    const int tid  = threadIdx.x;
    const int tr   = tid >> 5;   // warp id 0..7 -> 8 rows each
    const int tc   = tid & 31;   // lane -> 4 cols each

    // ---- stage edge metadata (pads replicate last edge; SH pads -> 0) ----
    const int pos0 = blockIdx.x * 64;
    const int nE   = (E_CNT - pos0 < 64) ? (E_CNT - pos0) : 64;
    if (tid < 64) {
        int sl = (tid < nE) ? tid : (nE - 1);
        int e  = g_eid[pos0 + sl];
        Es[tid] = e; Ss[tid] = src[e]; Ds[tid] = dst[e];
    }
    __syncthreads();

    // ---- stage EMB (gathered), W1s (scaled), SHs ----
#pragma unroll
    for (int t = 0; t < 4; t++) {              // EMB: 64 x 16 float4
        int li = tid + t * 256;
        int slot = li >> 4, f = li & 15;
        *(float4*)&EMB[slot * 64 + f * 4] =
            *(const float4*)&edge_emb[(size_t)Es[slot] * 64 + f * 4];
    }
#pragma unroll
    for (int t = 0; t < 8; t++) {              // W1s: 64 x 32 float4, *1/8
        int li = tid + t * 256;
        int r = li >> 5, f = li & 31;
        float4 v = *(const float4*)&W1[(size_t)r * 128 + f * 4];
        v.x *= 0.125f; v.y *= 0.125f; v.z *= 0.125f; v.w *= 0.125f;
        *(float4*)&W1s[r * 128 + f * 4] = v;
    }
    {                                          // SHs: 64 x 4 float4 (zero pads)
        int slot = tid >> 2, j = tid & 3;
        float4 v = make_float4(0.f, 0.f, 0.f, 0.f);
        if (slot < nE)
            v = *(const float4*)&edge_sh[(size_t)Es[slot] * 16 + j * 4];
        *(float4*)&SHs[slot * 16 + j * 4] = v;
    }
    __syncthreads();

    // ---- GEMM1: Hs = silu(EMB @ W1s), 64x128x64 ----
    {
        float acc[8][4];
#pragma unroll
        for (int i = 0; i < 8; i++)
#pragma unroll
            for (int j = 0; j < 4; j++) acc[i][j] = 0.f;

#pragma unroll 8
        for (int kk = 0; kk < 64; kk++) {
            float4 rb = *(const float4*)&W1s[kk * 128 + tc * 4];
#pragma unroll
            for (int i = 0; i < 8; i++) {
                float ra = EMB[(tr * 8 + i) * 64 + kk];   // warp-uniform broadcast
                acc[i][0] += ra * rb.x; acc[i][1] += ra * rb.y;
                acc[i][2] += ra * rb.z; acc[i][3] += ra * rb.w;
            }
        }
#pragma unroll
        for (int i = 0; i < 8; i++) {
            float4 v;
            v.x = acc[i][0] / (1.f + __expf(-acc[i][0]));
            v.y = acc[i][1] / (1.f + __expf(-acc[i][1]));
            v.z = acc[i][2] / (1.f + __expf(-acc[i][2]));
            v.w = acc[i][3] / (1.f + __expf(-acc[i][3]));
            *(float4*)&Hs[(tr * 8 + i) * 128 + tc * 4] = v;
        }
    }
    __syncthreads();   // Hs ready; EMB(Ws) and W1s(TPW) dead

    // ---- per-l: GEMM2 + fold x + run-length segment scatter ----
    const float w2s = 0.08838834764831845f;    // 1/sqrt(128)

    for (int l = 0; l < 4; l++) {
        float acc[8][4];
#pragma unroll
        for (int i = 0; i < 8; i++)
#pragma unroll
            for (int j = 0; j < 4; j++) acc[i][j] = 0.f;

        for (int k0 = 0; k0 < 128; k0 += 64) {
            if (k0) __syncthreads();           // Ws reuse guard within l
            // stage Ws[64][128] = W2[k0..k0+63][l*128..+128] * w2s
#pragma unroll
            for (int t = 0; t < 8; t++) {
                int li = tid + t * 256;
                int r = li >> 5, f = li & 31;
                float4 v = *(const float4*)&W2[(size_t)(k0 + r) * 512 + l * 128 + f * 4];
                v.x *= w2s; v.y *= w2s; v.z *= w2s; v.w *= w2s;
                *(float4*)&Ws[r * 128 + f * 4] = v;
            }
            __syncthreads();

#pragma unroll 8
            for (int kk = 0; kk < 64; kk++) {
                float4 rb = *(const float4*)&Ws[kk * 128 + tc * 4];
#pragma unroll
                for (int i = 0; i < 8; i++) {
                    float ra = Hs[(tr * 8 + i) * 128 + k0 + kk];  // broadcast
                    acc[i][0] += ra * rb.x; acc[i][1] += ra * rb.y;
                    acc[i][2] += ra * rb.z; acc[i][3] += ra * rb.w;
                }
            }
        }
        __syncthreads();   // all reads of Ws + previous TPW use complete

        // fold: TPW[row][c] = acc * x_src[src[row]][c]  (direct from L2, coalesced)
#pragma unroll
        for (int i = 0; i < 8; i++) {
            float4 xv = *(const float4*)&src_features[(size_t)Ss[tr * 8 + i] * 128 + tc * 4];
            float4 v;
            v.x = acc[i][0] * xv.x; v.y = acc[i][1] * xv.y;
            v.z = acc[i][2] * xv.z; v.w = acc[i][3] * xv.w;
            *(float4*)&TPW[(tr * 8 + i) * 128 + tc * 4] = v;
        }
        __syncthreads();

        // scatter: run-length reduce over 64 dst-sorted edges
        {
            const int d    = 2 * l + 1;
            const int soff = l * l;
            const int ob   = (l == 0) ? 0 : (l == 1) ? 128 : (l == 2) ? 512 : 1152;
            const int ncol = 128 * d;
            for (int q = tid; q < ncol; q += 256) {
                const int c = q / d;
                const int s = q - c * d;
                float a = 0.f;
                int cur = Ds[0];
#pragma unroll 8
                for (int t = 0; t < 64; t++) {
                    int dn = Ds[t];
                    if (dn != cur) {
                        atomicAdd(&out[(size_t)cur * OUTC + ob + q], a);
                        a = 0.f; cur = dn;
                    }
                    a += TPW[t * 128 + c] * SHs[t * 16 + soff + s];
                }
                atomicAdd(&out[(size_t)cur * OUTC + ob + q], a);
            }
        }
        __syncthreads();
    }
}

// ---------------- launch ----------------
extern "C" void kernel_launch(void* const* d_in, const int* in_sizes, int n_in,
                              void* d_out, int out_size)
{
    const float* src_features = (const float*)d_in[0];
    const float* edge_sh      = (const float*)d_in[1];
    const float* edge_emb     = (const float*)d_in[2];
    const float* W1           = (const float*)d_in[3];
    const float* W2           = (const float*)d_in[4];
    const int*   src          = (const int*)d_in[5];
    const int*   dst          = (const int*)d_in[6];
    float*       out          = (float*)d_out;
    (void)in_sizes; (void)n_in; (void)out_size;

    static bool attr_done = false;
    if (!attr_done) {
        cudaFuncSetAttribute(fused_k, cudaFuncAttributeMaxDynamicSharedMemorySize,
                             SMEM_BYTES);
        attr_done = true;
    }

    // CSR build
    zero_cnt_k<<<(NDST + 255) / 256, 256>>>();
    hist_k<<<(E_CNT + 255) / 256, 256>>>(dst);
    scan_k<<<1, 1024>>>();
    fill_k<<<(E_CNT + 255) / 256, 256>>>(dst);

    // zero output (atomic accumulation target)
    const int n4 = NDST * OUTC / 4;
    zero_out_k<<<(n4 + 255) / 256, 256>>>((float4*)out, n4);

    // fused MLP + TP + scatter (64 edges/block, 2 CTAs/SM)
    const int nblk = (E_CNT + 63) / 64;
    fused_k<<<nblk, 256, SMEM_BYTES>>>(src_features, edge_sh, edge_emb,
                                       W1, W2, src, dst, out);
}